// round 11
// baseline (speedup 1.0000x reference)
#include <cuda_runtime.h>

#define G 1024
#define RPT 8
#define BY 4          // block = 32 x 4 = 128 threads
#define NBLOCKS 1024  // grid 32 x 32

__device__ float2 g_part[NBLOCKS];
__device__ unsigned int g_cnt = 0;

#define C11 (1.0f / 0.91f)
#define C12 (0.3f / 0.91f)
#define C33 (0.35f / 0.91f)
#define A2c (2.0f * (C11 + C33))
#define BGc (0.5f * (C12 + C33))

// tri1 of a cell (corners a, b=a+j, c=a+i): s = C * d
#define TRI1(s0, s1, s2, ua, ub, uc)                                        \
    {                                                                       \
        float d0 = (uc).x - (ua).x;                                         \
        float d1 = (ub).y - (ua).y;                                         \
        float d2 = (ub).x + (uc).y - (ua).x - (ua).y;                       \
        s0 = C11 * d0 + C12 * d1;                                           \
        s1 = C12 * d0 + C11 * d1;                                           \
        s2 = C33 * d2;                                                      \
    }
// tri2 of a cell (corners b, d=b+i, c=d-j)
#define TRI2(t0, t1, t2, ub, ud, uc)                                        \
    {                                                                       \
        float e0 = (ud).x - (ub).x;                                         \
        float e1 = (ud).y - (uc).y;                                         \
        float e2 = (ud).x + (ud).y - (ub).y - (uc).x;                       \
        t0 = C11 * e0 + C12 * e1;                                           \
        t1 = C12 * e0 + C11 * e1;                                           \
        t2 = C33 * e2;                                                      \
    }

// One 8-row strip. All row offsets are compile-time immediates; the only
// runtime conditions inside the loop are the (warp-uniform) j-edge tests.
template <bool TOP, bool BOT>
__device__ __forceinline__ void do_strip(
    const float2* __restrict__ pu,   // up + i0*G + j
    const float2* __restrict__ pum,  // pu + djm
    const float2* __restrict__ pup,  // pu + djp
    const float2* __restrict__ pt,   // ut + i0*G + j
    const float2* __restrict__ ptp,  // pt + djp
    const int i0, const int j, const bool jint,
    float& vr, float& ve) {
    float2 pm0, pm1, pm2, pc0, pc1, pc2, pn0, pn1, pn2;
    float2 f0[2], f1[2], f2[2];      // up prefetch slots (distance 2)
    float2 tc0, tc1, tn0, tn1;
    float2 g0[2], g1[2];             // ut prefetch slots

    {
        const int rm = TOP ? 0 : -1;
        pm0 = __ldg(pum + rm * G); pm1 = __ldg(pu + rm * G); pm2 = __ldg(pup + rm * G);
    }
    pc0 = __ldg(pum);     pc1 = __ldg(pu);     pc2 = __ldg(pup);
    pn0 = __ldg(pum + G); pn1 = __ldg(pu + G); pn2 = __ldg(pup + G);
    f0[0] = __ldg(pum + 2 * G); f1[0] = __ldg(pu + 2 * G); f2[0] = __ldg(pup + 2 * G);
    tc0 = __ldg(pt);     tc1 = __ldg(ptp);
    tn0 = __ldg(pt + G); tn1 = __ldg(ptp + G);
    g0[0] = __ldg(pt + 2 * G); g1[0] = __ldg(ptp + 2 * G);

    #pragma unroll
    for (int k = 0; k < RPT; k++) {
        // prefetch row k+3 (clamped in the bottom strip) into slot (k+1)&1
        if (k <= RPT - 3) {
            const int r3 = (BOT && k + 3 > RPT - 1) ? (RPT - 1) : (k + 3);
            const int s = (k + 1) & 1;
            f0[s] = __ldg(pum + r3 * G); f1[s] = __ldg(pu + r3 * G); f2[s] = __ldg(pup + r3 * G);
            g0[s] = __ldg(pt + r3 * G);  g1[s] = __ldg(ptp + r3 * G);
        }

        const bool iint = !(TOP && k == 0) && !(BOT && k == RPT - 1);  // constexpr
        float Rx, Ry;
        if (iint && jint) {
            // interior 7-point stencil (u00/u22 cancel out)
            float Vx = pm1.x + pn1.x, Hx = pc0.x + pc2.x;
            float Vy = pm1.y + pn1.y, Hy = pc0.y + pc2.y;
            float Tx = 2.f * pc1.x - Vx - Hx + pn0.x + pm2.x;
            float Ty = 2.f * pc1.y - Vy - Hy + pn0.y + pm2.y;
            Rx = A2c * pc1.x - C11 * Vx - C33 * Hx + BGc * Ty;
            Ry = A2c * pc1.y - C11 * Hy - C33 * Vy + BGc * Tx;
        } else {
            // boundary: full masked 6-triangle path (verified)
            const int i = i0 + k;
            const float mA = (i < G - 1 && j < G - 1) ? 1.f : 0.f;
            const float mB = (i < G - 1 && j > 0) ? 1.f : 0.f;
            const float mC = (i > 0 && j < G - 1) ? 1.f : 0.f;
            const float mD = (i > 0 && j > 0) ? 1.f : 0.f;
            float sA0, sA1, sA2; TRI1(sA0, sA1, sA2, pc1, pc2, pn1);
            float sB0, sB1, sB2; TRI1(sB0, sB1, sB2, pc0, pc1, pn0);
            float tB0, tB1, tB2; TRI2(tB0, tB1, tB2, pc1, pn1, pn0);
            float sC0, sC1, sC2; TRI1(sC0, sC1, sC2, pm1, pm2, pc1);
            float tC0, tC1, tC2; TRI2(tC0, tC1, tC2, pm2, pc2, pc1);
            float tD0, tD1, tD2; TRI2(tD0, tD1, tD2, pm1, pc1, pc0);
            (void)sB0; (void)tB1; (void)sC1; (void)tC0;
            Rx = mA * (-0.5f) * (sA0 + sA2) + mB * 0.5f * (sB2 - tB0) +
                 mC * 0.5f * (sC0 - tC2)    + mD * 0.5f * (tD0 + tD2);
            Ry = mA * (-0.5f) * (sA1 + sA2) + mB * 0.5f * (sB1 - tB2) +
                 mC * 0.5f * (sC2 - tC1)    + mD * 0.5f * (tD1 + tD2);
        }
        vr += Rx * Rx + Ry * Ry;

        // energy of cell (i,j): invalid only at i==G-1 (BOT,k==7) and j==G-1
        if ((!BOT || k < RPT - 1) && j < G - 1) {
            float eax = pc1.x - tc0.x, eay = pc1.y - tc0.y;
            float ebx = pc2.x - tc1.x, eby = pc2.y - tc1.y;
            float ecx = pn1.x - tn0.x, ecy = pn1.y - tn0.y;
            float edx = pn2.x - tn1.x, edy = pn2.y - tn1.y;
            float d0 = ecx - eax, d1 = eby - eay, d2 = ebx + ecy - eax - eay;
            float e0 = edx - ebx, e1 = edy - ecy, e2 = edx + edy - eby - ecx;
            ve += C11 * (d0 * d0 + d1 * d1) + 2.f * C12 * (d0 * d1) +
                  C33 * (d2 * d2) +
                  C11 * (e0 * e0 + e1 * e1) + 2.f * C12 * (e0 * e1) +
                  C33 * (e2 * e2);
        }

        // shift window; consume prefetch slot k&1 (holds row k+2)
        if (k < RPT - 1) {
            const int s = k & 1;
            pm0 = pc0; pm1 = pc1; pm2 = pc2;
            pc0 = pn0; pc1 = pn1; pc2 = pn2;
            pn0 = f0[s]; pn1 = f1[s]; pn2 = f2[s];
            tc0 = tn0; tc1 = tn1;
            tn0 = g0[s]; tn1 = g1[s];
        }
    }
}

__global__ __launch_bounds__(128, 8) void pino_fused_kernel(
    const float2* __restrict__ up, const float2* __restrict__ ut,
    float* __restrict__ out) {
    const int j = blockIdx.x * 32 + threadIdx.x;
    const int i0 = (blockIdx.y * BY + threadIdx.y) * RPT;
    const int djm = (j > 0) ? -1 : 0;
    const int djp = (j < G - 1) ? 1 : 0;
    const bool jint = (j > 0) && (j < G - 1);

    const float2* pu = up + i0 * G + j;
    const float2* pt = ut + i0 * G + j;
    const float2* pum = pu + djm;
    const float2* pup = pu + djp;
    const float2* ptp = pt + djp;

    float vr = 0.f, ve = 0.f;
    if (i0 == 0) {
        do_strip<true, false>(pu, pum, pup, pt, ptp, i0, j, jint, vr, ve);
    } else if (i0 == G - RPT) {
        do_strip<false, true>(pu, pum, pup, pt, ptp, i0, j, jint, vr, ve);
    } else {
        do_strip<false, false>(pu, pum, pup, pt, ptp, i0, j, jint, vr, ve);
    }

    // ---- block reduction (4 warps) ----
    #pragma unroll
    for (int o = 16; o; o >>= 1) {
        vr += __shfl_down_sync(0xFFFFFFFFu, vr, o);
        ve += __shfl_down_sync(0xFFFFFFFFu, ve, o);
    }
    __shared__ float sr[BY], se[BY];
    __shared__ unsigned s_last;
    if (threadIdx.x == 0) { sr[threadIdx.y] = vr; se[threadIdx.y] = ve; }
    __syncthreads();
    if (threadIdx.x == 0 && threadIdx.y == 0) {
        float a = 0.f, b = 0.f;
        #pragma unroll
        for (int q = 0; q < BY; q++) { a += sr[q]; b += se[q]; }
        int bid = blockIdx.y * gridDim.x + blockIdx.x;
        g_part[bid] = make_float2(a, b);
        __threadfence();
        unsigned old = atomicAdd(&g_cnt, 1u);
        s_last = (old == NBLOCKS - 1) ? 1u : 0u;
    }
    __syncthreads();

    // ---- last block finishes the global reduction (fixed order -> deterministic) ----
    if (s_last) {
        const int t = threadIdx.y * 32 + threadIdx.x;  // 0..127
        double a = 0.0, b = 0.0;
        #pragma unroll
        for (int q = 0; q < NBLOCKS / 128; q++) {
            float2 v = g_part[q * 128 + t];
            a += (double)v.x;
            b += (double)v.y;
        }
        #pragma unroll
        for (int o = 16; o; o >>= 1) {
            a += __shfl_down_sync(0xFFFFFFFFu, a, o);
            b += __shfl_down_sync(0xFFFFFFFFu, b, o);
        }
        __shared__ double dr[BY], de[BY];
        if ((t & 31) == 0) { dr[t >> 5] = a; de[t >> 5] = b; }
        __syncthreads();
        if (t == 0) {
            double ta = 0.0, tb = 0.0;
            #pragma unroll
            for (int q = 0; q < BY; q++) { ta += dr[q]; tb += de[q]; }
            double leq = ta / (2.0 * (double)G * (double)G);  // mean(R^2)
            double len = 0.5 * tb;  // total_area telescopes to 1.0
            out[0] = (float)(0.1 * leq + 0.1 * len);
            g_cnt = 0;  // reset for next graph replay
        }
    }
}

extern "C" void kernel_launch(void* const* d_in, const int* in_sizes, int n_in,
                              void* d_out, int out_size) {
    const float2* up = (const float2*)d_in[0];  // u_pred (N,2)
    const float2* ut = (const float2*)d_in[1];  // u_true (N,2)
    (void)in_sizes; (void)n_in; (void)out_size;

    dim3 blk(32, BY);
    dim3 grd(G / 32, G / (BY * RPT));  // 32 x 32 = 1024 blocks of 128 threads
    pino_fused_kernel<<<grd, blk>>>(up, ut, (float*)d_out);
}